// round 12
// baseline (speedup 1.0000x reference)
#include <cuda_runtime.h>
#include <cuda_fp16.h>
#include <cstdint>

#define N_NODES 50000
#define N_HEDGES 10000
#define NNZ_INC 400000
#define NNZ_E 80000
#define NNZ_V 400000
#define D 128

#define NB_N 49
#define NB_V 49
#define NB_M 10
#define NB_E 10

// ---------------- scratch ----------------
__device__ float g_S1[(size_t)N_HEDGES * D];
__device__ float g_S2[(size_t)N_HEDGES * D];
__device__ float g_A [(size_t)N_HEDGES * D];
__device__ float g_E2[(size_t)N_HEDGES * D];
__device__ float g_GE[(size_t)N_HEDGES * D];
__device__ float g_V1[(size_t)N_NODES * D];
__device__ float g_c1[N_HEDGES];
__device__ float g_deg[N_HEDGES];

// fp16 mirrors (gather sources)
__device__ __half g_hvfeat[(size_t)N_NODES * D];
__device__ __half g_hefeat[(size_t)N_HEDGES * D];
__device__ __half g_hA   [(size_t)N_HEDGES * D];
__device__ __half g_hC   [(size_t)N_HEDGES * D];
__device__ __half g_hV2  [(size_t)N_NODES * D];
__device__ __half g_hV3  [(size_t)N_NODES * D];
__device__ __half g_hvout[(size_t)N_NODES * D];

// CSR scratch
__device__ int g_ecnt[N_HEDGES];  __device__ int g_eoff[N_HEDGES + 1];  __device__ int g_ecur[N_HEDGES];
__device__ int g_ncnt[N_NODES];   __device__ int g_noff[N_NODES + 1];   __device__ int g_ncur[N_NODES];
__device__ int g_vcnt[N_NODES];   __device__ int g_voff[N_NODES + 1];   __device__ int g_vcur[N_NODES];
__device__ int g_mcnt[N_HEDGES];  __device__ int g_moff[N_HEDGES + 1];  __device__ int g_mcur[N_HEDGES];
__device__ int   g_eidx[NNZ_INC];
__device__ int   g_nidx[NNZ_INC];
__device__ int   g_vidx[NNZ_V];
__device__ float g_vval[NNZ_V];
__device__ int   g_midx[NNZ_E];
__device__ float g_mval[NNZ_E];
__device__ int   g_bsumE[NB_E];
__device__ int   g_bsumNVM[NB_N + NB_V + NB_M];

// ---------------- helpers ----------------
__device__ __forceinline__ double ffma2(double a, double b, double c) {
    double d;
    asm("fma.rn.f32x2 %0, %1, %2, %3;" : "=d"(d) : "d"(a), "d"(b), "d"(c));
    return d;
}
__device__ __forceinline__ double dup2(float v) {
    double d;
    asm("mov.b64 %0, {%1, %1};" : "=d"(d) : "f"(v));
    return d;
}
__device__ __forceinline__ float2 unpk(double d) {
    float2 r;
    asm("mov.b64 {%0, %1}, %2;" : "=f"(r.x), "=f"(r.y) : "d"(d));
    return r;
}
__device__ __forceinline__ void sth4(__half* p, float4 v) {
    __half2 h0 = __floats2half2_rn(v.x, v.y);
    __half2 h1 = __floats2half2_rn(v.z, v.w);
    uint2 u;
    u.x = *(unsigned*)&h0;
    u.y = *(unsigned*)&h1;
    *(uint2*)p = u;
}
__device__ __forceinline__ void accum8(float4& a, float4& b, uint4 u) {
    __half2* h = (__half2*)&u;
    float2 f0 = __half22float2(h[0]), f1 = __half22float2(h[1]);
    float2 f2 = __half22float2(h[2]), f3 = __half22float2(h[3]);
    a.x += f0.x; a.y += f0.y; a.z += f1.x; a.w += f1.y;
    b.x += f2.x; b.y += f2.y; b.z += f3.x; b.w += f3.y;
}
__device__ __forceinline__ void faccum8(float4& a, float4& b, float s, uint4 u) {
    __half2* h = (__half2*)&u;
    float2 f0 = __half22float2(h[0]), f1 = __half22float2(h[1]);
    float2 f2 = __half22float2(h[2]), f3 = __half22float2(h[3]);
    a.x = fmaf(s, f0.x, a.x); a.y = fmaf(s, f0.y, a.y);
    a.z = fmaf(s, f1.x, a.z); a.w = fmaf(s, f1.y, a.w);
    b.x = fmaf(s, f2.x, b.x); b.y = fmaf(s, f2.y, b.y);
    b.z = fmaf(s, f3.x, b.z); b.w = fmaf(s, f3.y, b.w);
}
__device__ __forceinline__ void red16(float4& a) {
    a.x += __shfl_xor_sync(0xffffffffu, a.x, 16);
    a.y += __shfl_xor_sync(0xffffffffu, a.y, 16);
    a.z += __shfl_xor_sync(0xffffffffu, a.z, 16);
    a.w += __shfl_xor_sync(0xffffffffu, a.w, 16);
}
__device__ __forceinline__ void m4(float4& a, float4 c) {
    a.x += c.x; a.y += c.y; a.z += c.z; a.w += c.w;
}
__device__ __forceinline__ void sth8(__half* p, float4 a, float4 b) {
    __half2 h0 = __floats2half2_rn(a.x, a.y), h1 = __floats2half2_rn(a.z, a.w);
    __half2 h2 = __floats2half2_rn(b.x, b.y), h3 = __floats2half2_rn(b.z, b.w);
    uint4 u;
    u.x = *(unsigned*)&h0; u.y = *(unsigned*)&h1;
    u.z = *(unsigned*)&h2; u.w = *(unsigned*)&h3;
    *(uint4*)p = u;
}

// ---------------- input conversion ----------------
__global__ void conv_feat_kernel(const float* __restrict__ vf, const float* __restrict__ ef) {
    int i = blockIdx.x * blockDim.x + threadIdx.x;
    int stride = gridDim.x * blockDim.x;
    const int NV = N_NODES * D / 4, NE = N_HEDGES * D / 4;
    for (int k = i; k < NV; k += stride)
        sth4(g_hvfeat + (size_t)k * 4, ((const float4*)vf)[k]);
    for (int k = i; k < NE; k += stride)
        sth4(g_hefeat + (size_t)k * 4, ((const float4*)ef)[k]);
}

// ---------------- CSR build ----------------
__global__ void zeroE_kernel() {
    int i = blockIdx.x * blockDim.x + threadIdx.x;
    if (i < N_HEDGES) g_ecnt[i] = 0;
}
__global__ void zeroNVM_kernel() {
    int i = blockIdx.x * blockDim.x + threadIdx.x;
    int stride = gridDim.x * blockDim.x;
    for (int k = i; k < N_NODES; k += stride) { g_ncnt[k] = 0; g_vcnt[k] = 0; }
    for (int k = i; k < N_HEDGES; k += stride) g_mcnt[k] = 0;
}
__global__ void histE_kernel(const int* __restrict__ dst) {
    int k = blockIdx.x * blockDim.x + threadIdx.x;
    if (k < NNZ_INC) atomicAdd(&g_ecnt[__ldg(dst + k)], 1);
}
__global__ void histNVM_kernel(const int* __restrict__ src,
                               const int* __restrict__ vrows,
                               const int* __restrict__ mrows) {
    int k = blockIdx.x * blockDim.x + threadIdx.x;
    if (k < NNZ_INC) {
        atomicAdd(&g_ncnt[__ldg(src + k)], 1);
        atomicAdd(&g_vcnt[__ldg(vrows + k)], 1);
        if (k < NNZ_E) atomicAdd(&g_mcnt[__ldg(mrows + k)], 1);
    }
}
__device__ void scan_p1_body(const int* __restrict__ cnt, int* __restrict__ off,
                             int n, int lblk, int* __restrict__ bsum) {
    __shared__ int warpsum[8];
    int t = threadIdx.x;
    int lane = t & 31, wid = t >> 5;
    int base = lblk * 1024 + t * 4;
    int v0 = 0, v1 = 0, v2 = 0, v3 = 0;
    if (base + 3 < n) {
        int4 vv = *(const int4*)(cnt + base);
        v0 = vv.x; v1 = vv.y; v2 = vv.z; v3 = vv.w;
    } else {
        if (base     < n) v0 = cnt[base];
        if (base + 1 < n) v1 = cnt[base + 1];
        if (base + 2 < n) v2 = cnt[base + 2];
        if (base + 3 < n) v3 = cnt[base + 3];
    }
    int ts = v0 + v1 + v2 + v3;
    int incl = ts;
#pragma unroll
    for (int dlt = 1; dlt < 32; dlt <<= 1) {
        int u = __shfl_up_sync(0xffffffff, incl, dlt);
        if (lane >= dlt) incl += u;
    }
    if (lane == 31) warpsum[wid] = incl;
    __syncthreads();
    if (wid == 0) {
        int ws = (lane < 8) ? warpsum[lane] : 0;
        int wincl = ws;
#pragma unroll
        for (int dlt = 1; dlt < 8; dlt <<= 1) {
            int u = __shfl_up_sync(0xffffffff, wincl, dlt);
            if (lane >= dlt) wincl += u;
        }
        if (lane < 8) warpsum[lane] = wincl - ws;
        if (lane == 7) bsum[lblk] = wincl;
    }
    __syncthreads();
    int ex = warpsum[wid] + incl - ts;
    if (base     < n) off[base]     = ex;
    if (base + 1 < n) off[base + 1] = ex + v0;
    if (base + 2 < n) off[base + 2] = ex + v0 + v1;
    if (base + 3 < n) off[base + 3] = ex + v0 + v1 + v2;
}
__device__ void scan_p2_warp(int* bsum, int nblk, int* off, int n, int lane) {
    int carry = 0;
    for (int i0 = 0; i0 < nblk; i0 += 32) {
        int i = i0 + lane;
        int v = (i < nblk) ? bsum[i] : 0;
        int incl = v;
#pragma unroll
        for (int dlt = 1; dlt < 32; dlt <<= 1) {
            int u = __shfl_up_sync(0xffffffff, incl, dlt);
            if (lane >= dlt) incl += u;
        }
        if (i < nblk) bsum[i] = carry + incl - v;
        carry += __shfl_sync(0xffffffff, incl, 31);
    }
    if (lane == 0) off[n] = carry;
}
__device__ void scan_p3_body(int* __restrict__ off, int* __restrict__ cur,
                             int n, int lblk, const int* __restrict__ bsum) {
    int add = bsum[lblk];
    int base = lblk * 1024 + threadIdx.x * 4;
#pragma unroll
    for (int k = 0; k < 4; k++) {
        int i = base + k;
        if (i < n) { int v = off[i] + add; off[i] = v; cur[i] = v; }
    }
}
__device__ __forceinline__ void nvm_seg(int blk, const int*& cnt, int*& off, int*& cur,
                                        int& n, int& lblk, int*& bsum) {
    if (blk < NB_N)            { cnt = g_ncnt; off = g_noff; cur = g_ncur; n = N_NODES;  lblk = blk;               bsum = g_bsumNVM; }
    else if (blk < NB_N+NB_V)  { cnt = g_vcnt; off = g_voff; cur = g_vcur; n = N_NODES;  lblk = blk - NB_N;        bsum = g_bsumNVM + NB_N; }
    else                       { cnt = g_mcnt; off = g_moff; cur = g_mcur; n = N_HEDGES; lblk = blk - NB_N - NB_V; bsum = g_bsumNVM + NB_N + NB_V; }
}
__global__ void scanNVM_p1() {
    const int* cnt; int *off, *cur, *bsum; int n, lblk;
    nvm_seg(blockIdx.x, cnt, off, cur, n, lblk, bsum);
    scan_p1_body(cnt, off, n, lblk, bsum);
}
__global__ void scanNVM_p2() {
    int wid = threadIdx.x >> 5, lane = threadIdx.x & 31;
    if (wid == 0)      scan_p2_warp(g_bsumNVM,             NB_N, g_noff, N_NODES,  lane);
    else if (wid == 1) scan_p2_warp(g_bsumNVM + NB_N,      NB_V, g_voff, N_NODES,  lane);
    else if (wid == 2) scan_p2_warp(g_bsumNVM + NB_N+NB_V, NB_M, g_moff, N_HEDGES, lane);
}
__global__ void scanNVM_p3() {
    const int* cnt; int *off, *cur, *bsum; int n, lblk;
    nvm_seg(blockIdx.x, cnt, off, cur, n, lblk, bsum);
    scan_p3_body(off, cur, n, lblk, bsum);
}
__global__ void scanE_p1() { scan_p1_body(g_ecnt, g_eoff, N_HEDGES, blockIdx.x, g_bsumE); }
__global__ void scanE_p2() {
    if (threadIdx.x < 32) scan_p2_warp(g_bsumE, NB_E, g_eoff, N_HEDGES, threadIdx.x);
}
__global__ void scanE_p3() { scan_p3_body(g_eoff, g_ecur, N_HEDGES, blockIdx.x, g_bsumE); }

__global__ void fillE_kernel(const int* __restrict__ src, const int* __restrict__ dst) {
    int k = blockIdx.x * blockDim.x + threadIdx.x;
    if (k >= NNZ_INC) return;
    int d = __ldg(dst + k);
    int pe = atomicAdd(&g_ecur[d], 1);
    g_eidx[pe] = __ldg(src + k);
}
__global__ void fillNVM_kernel(const int* __restrict__ src, const int* __restrict__ dst,
                               const int* __restrict__ vrows, const int* __restrict__ vcols,
                               const float* __restrict__ vvals,
                               const int* __restrict__ mrows, const int* __restrict__ mcols,
                               const float* __restrict__ mvals) {
    int k = blockIdx.x * blockDim.x + threadIdx.x;
    if (k >= NNZ_INC) return;
    int s = __ldg(src + k), r = __ldg(vrows + k);
    int pn = atomicAdd(&g_ncur[s], 1);
    g_nidx[pn] = __ldg(dst + k);
    int pv = atomicAdd(&g_vcur[r], 1);
    g_vidx[pv] = __ldg(vcols + k);
    g_vval[pv] = __ldg(vvals + k);
    if (k < NNZ_E) {
        int mr = __ldg(mrows + k);
        int pm = atomicAdd(&g_mcur[mr], 1);
        g_midx[pm] = __ldg(mcols + k);
        g_mval[pm] = __ldg(mvals + k);
    }
}

// ---------------- pair-mode gathers, unroll 8 (4×16B loads in flight per half-warp) ----
__global__ void edge_gather1_h(const float* __restrict__ invDV) {
    int w = (blockIdx.x * blockDim.x + threadIdx.x) >> 5;
    int lane = threadIdx.x & 31;
    if (w >= N_HEDGES) return;
    int half = lane >> 4, hl = lane & 15;
    int b = g_eoff[w], e = g_eoff[w + 1];
    float4 aA = make_float4(0.f,0.f,0.f,0.f), aB = aA, cA = aA, cB = aA;
    float cs = 0.f;
    int j = b;
    for (; j + 8 <= e; j += 8) {
        int s0 = g_eidx[j     + half];
        int s1 = g_eidx[j + 2 + half];
        int s2 = g_eidx[j + 4 + half];
        int s3 = g_eidx[j + 6 + half];
        float i0 = invDV[s0], i1 = invDV[s1], i2 = invDV[s2], i3 = invDV[s3];
        uint4 u0 = *(const uint4*)(g_hvfeat + (size_t)s0 * D + hl * 8);
        uint4 u1 = *(const uint4*)(g_hvfeat + (size_t)s1 * D + hl * 8);
        uint4 u2 = *(const uint4*)(g_hvfeat + (size_t)s2 * D + hl * 8);
        uint4 u3 = *(const uint4*)(g_hvfeat + (size_t)s3 * D + hl * 8);
        faccum8(aA, aB, i0, u0);
        faccum8(cA, cB, i1, u1);
        faccum8(aA, aB, i2, u2);
        faccum8(cA, cB, i3, u3);
        if (hl == 0) cs += i0 + i1 + i2 + i3;
    }
    for (; j + 2 <= e; j += 2) {
        int s0 = g_eidx[j + half];
        float i0 = invDV[s0];
        uint4 u0 = *(const uint4*)(g_hvfeat + (size_t)s0 * D + hl * 8);
        faccum8(aA, aB, i0, u0);
        if (hl == 0) cs += i0;
    }
    if (j < e && half == 0) {
        int s0 = g_eidx[j];
        float i0 = invDV[s0];
        uint4 u0 = *(const uint4*)(g_hvfeat + (size_t)s0 * D + hl * 8);
        faccum8(aA, aB, i0, u0);
        if (hl == 0) cs += i0;
    }
    m4(aA, cA); m4(aB, cB);
    red16(aA); red16(aB);
    cs += __shfl_xor_sync(0xffffffffu, cs, 16);
    if (half == 0) {
        float* sp = g_S1 + (size_t)w * D + hl * 8;
        *(float4*)sp = aA;
        *(float4*)(sp + 4) = aB;
        if (hl == 0) { g_c1[w] = cs; g_deg[w] = (float)(e - b); }
    }
}

__global__ void gather_sum_h2h(const int* __restrict__ off, const int* __restrict__ idx,
                               const __half* __restrict__ Xh, __half* __restrict__ Yh, int R) {
    int w = (blockIdx.x * blockDim.x + threadIdx.x) >> 5;
    int lane = threadIdx.x & 31;
    if (w >= R) return;
    int half = lane >> 4, hl = lane & 15;
    int b = off[w], e = off[w + 1];
    float4 aA = make_float4(0.f,0.f,0.f,0.f), aB = aA, cA = aA, cB = aA;
    int j = b;
    for (; j + 8 <= e; j += 8) {
        int s0 = idx[j     + half], s1 = idx[j + 2 + half];
        int s2 = idx[j + 4 + half], s3 = idx[j + 6 + half];
        uint4 u0 = *(const uint4*)(Xh + (size_t)s0 * D + hl * 8);
        uint4 u1 = *(const uint4*)(Xh + (size_t)s1 * D + hl * 8);
        uint4 u2 = *(const uint4*)(Xh + (size_t)s2 * D + hl * 8);
        uint4 u3 = *(const uint4*)(Xh + (size_t)s3 * D + hl * 8);
        accum8(aA, aB, u0);
        accum8(cA, cB, u1);
        accum8(aA, aB, u2);
        accum8(cA, cB, u3);
    }
    for (; j + 2 <= e; j += 2) {
        int s0 = idx[j + half];
        uint4 u0 = *(const uint4*)(Xh + (size_t)s0 * D + hl * 8);
        accum8(aA, aB, u0);
    }
    if (j < e && half == 0) {
        int s0 = idx[j];
        uint4 u0 = *(const uint4*)(Xh + (size_t)s0 * D + hl * 8);
        accum8(aA, aB, u0);
    }
    m4(aA, cA); m4(aB, cB);
    red16(aA); red16(aB);
    if (half == 0) sth8(Yh + (size_t)w * D + hl * 8, aA, aB);
}

__global__ void gather_sum_h2f(const int* __restrict__ off, const int* __restrict__ idx,
                               const __half* __restrict__ Xh, const __half* __restrict__ baseh,
                               float* __restrict__ Yf, int R) {
    int w = (blockIdx.x * blockDim.x + threadIdx.x) >> 5;
    int lane = threadIdx.x & 31;
    if (w >= R) return;
    int half = lane >> 4, hl = lane & 15;
    int b = off[w], e = off[w + 1];
    float4 aA = make_float4(0.f,0.f,0.f,0.f), aB = aA, cA = aA, cB = aA;
    int j = b;
    for (; j + 8 <= e; j += 8) {
        int s0 = idx[j     + half], s1 = idx[j + 2 + half];
        int s2 = idx[j + 4 + half], s3 = idx[j + 6 + half];
        uint4 u0 = *(const uint4*)(Xh + (size_t)s0 * D + hl * 8);
        uint4 u1 = *(const uint4*)(Xh + (size_t)s1 * D + hl * 8);
        uint4 u2 = *(const uint4*)(Xh + (size_t)s2 * D + hl * 8);
        uint4 u3 = *(const uint4*)(Xh + (size_t)s3 * D + hl * 8);
        accum8(aA, aB, u0);
        accum8(cA, cB, u1);
        accum8(aA, aB, u2);
        accum8(cA, cB, u3);
    }
    for (; j + 2 <= e; j += 2) {
        int s0 = idx[j + half];
        uint4 u0 = *(const uint4*)(Xh + (size_t)s0 * D + hl * 8);
        accum8(aA, aB, u0);
    }
    if (j < e && half == 0) {
        int s0 = idx[j];
        uint4 u0 = *(const uint4*)(Xh + (size_t)s0 * D + hl * 8);
        accum8(aA, aB, u0);
    }
    m4(aA, cA); m4(aB, cB);
    red16(aA); red16(aB);
    if (half == 0) {
        if (baseh) {
            uint4 ub = *(const uint4*)(baseh + (size_t)w * D + hl * 8);
            accum8(aA, aB, ub);
        }
        float* yp = Yf + (size_t)w * D + hl * 8;
        *(float4*)yp = aA;
        *(float4*)(yp + 4) = aB;
    }
}

__global__ void gather_wsum_h2h(const int* __restrict__ off, const int* __restrict__ idx,
                                const float* __restrict__ wv, const __half* __restrict__ Xh,
                                __half* __restrict__ Yh, int R) {
    int w = (blockIdx.x * blockDim.x + threadIdx.x) >> 5;
    int lane = threadIdx.x & 31;
    if (w >= R) return;
    int half = lane >> 4, hl = lane & 15;
    int b = off[w], e = off[w + 1];
    float4 aA = make_float4(0.f,0.f,0.f,0.f), aB = aA, cA = aA, cB = aA;
    int j = b;
    for (; j + 8 <= e; j += 8) {
        int s0 = idx[j     + half], s1 = idx[j + 2 + half];
        int s2 = idx[j + 4 + half], s3 = idx[j + 6 + half];
        float w0 = wv[j     + half], w1 = wv[j + 2 + half];
        float w2 = wv[j + 4 + half], w3 = wv[j + 6 + half];
        uint4 u0 = *(const uint4*)(Xh + (size_t)s0 * D + hl * 8);
        uint4 u1 = *(const uint4*)(Xh + (size_t)s1 * D + hl * 8);
        uint4 u2 = *(const uint4*)(Xh + (size_t)s2 * D + hl * 8);
        uint4 u3 = *(const uint4*)(Xh + (size_t)s3 * D + hl * 8);
        faccum8(aA, aB, w0, u0);
        faccum8(cA, cB, w1, u1);
        faccum8(aA, aB, w2, u2);
        faccum8(cA, cB, w3, u3);
    }
    for (; j + 2 <= e; j += 2) {
        int s0 = idx[j + half];
        float w0 = wv[j + half];
        uint4 u0 = *(const uint4*)(Xh + (size_t)s0 * D + hl * 8);
        faccum8(aA, aB, w0, u0);
    }
    if (j < e && half == 0) {
        int s0 = idx[j];
        float w0 = wv[j];
        uint4 u0 = *(const uint4*)(Xh + (size_t)s0 * D + hl * 8);
        faccum8(aA, aB, w0, u0);
    }
    m4(aA, cA); m4(aB, cB);
    red16(aA); red16(aB);
    if (half == 0) sth8(Yh + (size_t)w * D + hl * 8, aA, aB);
}

// ---------------- tiled GEMM ----------------
#define GEMM_RT 64
template <int K, bool CONCAT>
__global__ void gemm_tiled_kernel(const float* __restrict__ X, const float* __restrict__ ef,
                                  const float* __restrict__ coef, const float* __restrict__ oscale,
                                  const float* __restrict__ addend,
                                  const float* __restrict__ W, const float* __restrict__ bias,
                                  float* __restrict__ Y, __half* __restrict__ Yh,
                                  int R, int do_relu) {
    extern __shared__ float sh[];
    float* sWt = sh;
    float* sXt = sh + K * 132;
    const int tid = threadIdx.x;
    const int tc = tid & 31;
    const int tr = tid >> 5;
    const int row0 = blockIdx.x * GEMM_RT;

    for (int idx = tid; idx < 128 * K; idx += 256) {
        int col = idx / K, k = idx - col * K;
        sWt[k * 132 + col] = W[idx];
    }
    constexpr int NQ = K / 4;
    for (int idx = tid; idx < GEMM_RT * NQ; idx += 256) {
        int row = idx / NQ, kq = idx - row * NQ;
        int kk = kq * 4;
        int gr = row0 + row;
        float4 val = make_float4(0.f, 0.f, 0.f, 0.f);
        if (gr < R) {
            if (!CONCAT || kk < 128) {
                val = *(const float4*)(X + (size_t)gr * 128 + kk);
            } else {
                float cf = coef[gr];
                float4 ev = *(const float4*)(ef + (size_t)gr * 128 + (kk - 128));
                val.x = cf * ev.x; val.y = cf * ev.y; val.z = cf * ev.z; val.w = cf * ev.w;
            }
        }
        float* dstp = sXt + (size_t)kk * 68 + row;
        dstp[0]   = val.x;
        dstp[68]  = val.y;
        dstp[136] = val.z;
        dstp[204] = val.w;
    }
    __syncthreads();

    double acc[4][4];
#pragma unroll
    for (int p = 0; p < 4; p++)
#pragma unroll
        for (int c = 0; c < 4; c++) acc[p][c] = 0.0;

    const int c0 = tc * 4;
    const int r0 = tr * 8;
#pragma unroll 8
    for (int k = 0; k < K; k++) {
        float4 wv = *(const float4*)(sWt + k * 132 + c0);
        double2 xd01 = *(const double2*)(sXt + k * 68 + r0);
        double2 xd23 = *(const double2*)(sXt + k * 68 + r0 + 4);
        double w0 = dup2(wv.x), w1 = dup2(wv.y), w2 = dup2(wv.z), w3 = dup2(wv.w);
        acc[0][0] = ffma2(xd01.x, w0, acc[0][0]);
        acc[0][1] = ffma2(xd01.x, w1, acc[0][1]);
        acc[0][2] = ffma2(xd01.x, w2, acc[0][2]);
        acc[0][3] = ffma2(xd01.x, w3, acc[0][3]);
        acc[1][0] = ffma2(xd01.y, w0, acc[1][0]);
        acc[1][1] = ffma2(xd01.y, w1, acc[1][1]);
        acc[1][2] = ffma2(xd01.y, w2, acc[1][2]);
        acc[1][3] = ffma2(xd01.y, w3, acc[1][3]);
        acc[2][0] = ffma2(xd23.x, w0, acc[2][0]);
        acc[2][1] = ffma2(xd23.x, w1, acc[2][1]);
        acc[2][2] = ffma2(xd23.x, w2, acc[2][2]);
        acc[2][3] = ffma2(xd23.x, w3, acc[2][3]);
        acc[3][0] = ffma2(xd23.y, w0, acc[3][0]);
        acc[3][1] = ffma2(xd23.y, w1, acc[3][1]);
        acc[3][2] = ffma2(xd23.y, w2, acc[3][2]);
        acc[3][3] = ffma2(xd23.y, w3, acc[3][3]);
    }

    float4 bv = make_float4(0.f, 0.f, 0.f, 0.f);
    if (bias) bv = *(const float4*)(bias + c0);
    int row_base = row0 + r0;
#pragma unroll
    for (int p = 0; p < 4; p++) {
        float2 y0 = unpk(acc[p][0]);
        float2 y1 = unpk(acc[p][1]);
        float2 y2 = unpk(acc[p][2]);
        float2 y3 = unpk(acc[p][3]);
#pragma unroll
        for (int h = 0; h < 2; h++) {
            int row = row_base + 2 * p + h;
            if (row >= R) continue;
            float4 o = (h == 0) ? make_float4(y0.x, y1.x, y2.x, y3.x)
                                : make_float4(y0.y, y1.y, y2.y, y3.y);
            if (bias) {
                float cf = coef ? coef[row] : 1.f;
                o.x = fmaf(cf, bv.x, o.x); o.y = fmaf(cf, bv.y, o.y);
                o.z = fmaf(cf, bv.z, o.z); o.w = fmaf(cf, bv.w, o.w);
            }
            if (oscale) {
                float os = oscale[row];
                o.x *= os; o.y *= os; o.z *= os; o.w *= os;
            }
            if (addend) {
                float4 ad = *(const float4*)(addend + (size_t)row * 128 + c0);
                o.x += ad.x; o.y += ad.y; o.z += ad.z; o.w += ad.w;
            }
            if (do_relu) {
                o.x = fmaxf(o.x, 0.f); o.y = fmaxf(o.y, 0.f);
                o.z = fmaxf(o.z, 0.f); o.w = fmaxf(o.w, 0.f);
            }
            *(float4*)(Y + (size_t)row * 128 + c0) = o;
            if (Yh) sth4(Yh + (size_t)row * 128 + c0, o);
        }
    }
}

// ---------------- launch ----------------
extern "C" void kernel_launch(void* const* d_in, const int* in_sizes, int n_in,
                              void* d_out, int out_size) {
    const float* vfeat    = (const float*)d_in[0];
    const float* efeat    = (const float*)d_in[1];
    const float* invDV    = (const float*)d_in[2];
    const float* invDE    = (const float*)d_in[3];
    const int*   inc_src  = (const int*)d_in[4];
    const int*   inc_dst  = (const int*)d_in[5];
    const int*   emat_rows = (const int*)d_in[6];
    const int*   emat_cols = (const int*)d_in[7];
    const float* emat_vals = (const float*)d_in[8];
    const int*   vmat_rows = (const int*)d_in[9];
    const int*   vmat_cols = (const int*)d_in[10];
    const float* vmat_vals = (const float*)d_in[11];
    const float* Wv      = (const float*)d_in[12];
    const float* We      = (const float*)d_in[13];
    const float* psi1_W  = (const float*)d_in[14];
    const float* psi1_b  = (const float*)d_in[15];
    const float* psi2_W  = (const float*)d_in[16];
    const float* psi2_b  = (const float*)d_in[17];

    float* out  = (float*)d_out;
    float* vout = out;
    float* eout = out + (size_t)N_NODES * D;

    float *pS1, *pS2, *pA, *pE2, *pGE, *pV1, *pc1, *pdeg;
    int *peoff, *peidx, *pnoff, *pnidx, *pvoff, *pvidx, *pmoff, *pmidx;
    float *pvval, *pmval;
    __half *phA, *phC, *phV2, *phV3, *phvout, *phvfeat, *phefeat;
    cudaGetSymbolAddress((void**)&pS1, g_S1);
    cudaGetSymbolAddress((void**)&pS2, g_S2);
    cudaGetSymbolAddress((void**)&pA,  g_A);
    cudaGetSymbolAddress((void**)&pE2, g_E2);
    cudaGetSymbolAddress((void**)&pGE, g_GE);
    cudaGetSymbolAddress((void**)&pV1, g_V1);
    cudaGetSymbolAddress((void**)&pc1, g_c1);
    cudaGetSymbolAddress((void**)&pdeg, g_deg);
    cudaGetSymbolAddress((void**)&peoff, g_eoff);
    cudaGetSymbolAddress((void**)&peidx, g_eidx);
    cudaGetSymbolAddress((void**)&pnoff, g_noff);
    cudaGetSymbolAddress((void**)&pnidx, g_nidx);
    cudaGetSymbolAddress((void**)&pvoff, g_voff);
    cudaGetSymbolAddress((void**)&pvidx, g_vidx);
    cudaGetSymbolAddress((void**)&pmoff, g_moff);
    cudaGetSymbolAddress((void**)&pmidx, g_midx);
    cudaGetSymbolAddress((void**)&pvval, g_vval);
    cudaGetSymbolAddress((void**)&pmval, g_mval);
    cudaGetSymbolAddress((void**)&phA,    g_hA);
    cudaGetSymbolAddress((void**)&phC,    g_hC);
    cudaGetSymbolAddress((void**)&phV2,   g_hV2);
    cudaGetSymbolAddress((void**)&phV3,   g_hV3);
    cudaGetSymbolAddress((void**)&phvout, g_hvout);
    cudaGetSymbolAddress((void**)&phvfeat, g_hvfeat);
    cudaGetSymbolAddress((void**)&phefeat, g_hefeat);

    size_t smem128 = (size_t)(128 * 132 + 128 * 68) * sizeof(float);
    size_t smem256 = (size_t)(256 * 132 + 256 * 68) * sizeof(float);
    cudaFuncSetAttribute(gemm_tiled_kernel<128, false>,
                         cudaFuncAttributeMaxDynamicSharedMemorySize, (int)smem128);
    cudaFuncSetAttribute(gemm_tiled_kernel<256, true>,
                         cudaFuncAttributeMaxDynamicSharedMemorySize, (int)smem256);

    static cudaStream_t s1 = nullptr;
    static cudaEvent_t evRoot = nullptr, evConv = nullptr, evM = nullptr, evV2 = nullptr;
    static cudaEvent_t evECSR = nullptr, evGE = nullptr, evV3 = nullptr;
    if (s1 == nullptr) {
        cudaStreamCreateWithFlags(&s1, cudaStreamNonBlocking);
        cudaEventCreateWithFlags(&evRoot, cudaEventDisableTiming);
        cudaEventCreateWithFlags(&evConv, cudaEventDisableTiming);
        cudaEventCreateWithFlags(&evM,    cudaEventDisableTiming);
        cudaEventCreateWithFlags(&evV2,   cudaEventDisableTiming);
        cudaEventCreateWithFlags(&evECSR, cudaEventDisableTiming);
        cudaEventCreateWithFlags(&evGE,   cudaEventDisableTiming);
        cudaEventCreateWithFlags(&evV3,   cudaEventDisableTiming);
    }

    const int BLK = 256;
    int ew = (N_HEDGES + 7) / 8;
    int nw = (N_NODES + 7) / 8;
    int gemmN = (N_NODES + GEMM_RT - 1) / GEMM_RT;
    int gemmE = (N_HEDGES + GEMM_RT - 1) / GEMM_RT;
    int nnz_blk = (NNZ_INC + BLK - 1) / BLK;

    cudaEventRecord(evRoot, 0);
    cudaStreamWaitEvent(s1, evRoot, 0);

    // --- stream B chain, part 1 ---
    conv_feat_kernel<<<1024, 256, 0, s1>>>(vfeat, efeat);
    cudaEventRecord(evConv, s1);
    zeroNVM_kernel<<<256, 256, 0, s1>>>();
    histNVM_kernel<<<nnz_blk, BLK, 0, s1>>>(inc_src, vmat_rows, emat_rows);
    scanNVM_p1<<<NB_N + NB_V + NB_M, 256, 0, s1>>>();
    scanNVM_p2<<<1, 96, 0, s1>>>();
    scanNVM_p3<<<NB_N + NB_V + NB_M, 256, 0, s1>>>();
    fillNVM_kernel<<<nnz_blk, BLK, 0, s1>>>(inc_src, inc_dst, vmat_rows, vmat_cols, vmat_vals,
                                            emat_rows, emat_cols, emat_vals);
    cudaEventRecord(evM, s1);
    gather_sum_h2h<<<nw, BLK, 0, s1>>>(pnoff, pnidx, phefeat, phV2, N_NODES);       // hV2
    cudaEventRecord(evV2, s1);
    gather_wsum_h2h<<<nw, BLK, 0, s1>>>(pvoff, pvidx, pvval, phV2, phV3, N_NODES);  // hV3
    cudaEventRecord(evV3, s1);

    // --- stream A: E-CSR build (record evECSR BEFORE stream B waits on it) ---
    zeroE_kernel<<<(N_HEDGES + 255) / 256, 256>>>();
    histE_kernel<<<nnz_blk, BLK>>>(inc_dst);
    scanE_p1<<<NB_E, 256>>>();
    scanE_p2<<<1, 32>>>();
    scanE_p3<<<NB_E, 256>>>();
    fillE_kernel<<<nnz_blk, BLK>>>(inc_src, inc_dst);
    cudaEventRecord(evECSR, 0);

    // --- stream B chain, part 2: GE gather (overlaps vout GEMM) ---
    cudaStreamWaitEvent(s1, evECSR, 0);
    gather_sum_h2f<<<ew, BLK, 0, s1>>>(peoff, peidx, phV3, nullptr, pGE, N_HEDGES); // GE
    cudaEventRecord(evGE, s1);

    // --- stream A critical chain (continued) ---
    cudaStreamWaitEvent(0, evConv, 0);
    edge_gather1_h<<<ew, BLK>>>(invDV);                                             // S1, c1, deg
    gemm_tiled_kernel<256, true><<<gemmE, 256, smem256>>>(
        pS1, efeat, pc1, nullptr, nullptr, psi1_W, psi1_b, pA, phA, N_HEDGES, 0);   // A (+hA)
    cudaStreamWaitEvent(0, evM, 0);
    gather_wsum_h2h<<<ew, BLK>>>(pmoff, pmidx, pmval, phA, phC, N_HEDGES);          // hC
    cudaStreamWaitEvent(0, evV2, 0);
    gather_sum_h2f<<<nw, BLK>>>(pnoff, pnidx, phC, phV2, pV1, N_NODES);             // V1 = V2 + ΣC
    gemm_tiled_kernel<128, false><<<gemmN, 256, smem128>>>(
        pV1, nullptr, nullptr, nullptr, nullptr, Wv, nullptr, vout, phvout, N_NODES, 1); // vout (+h)
    gather_sum_h2f<<<ew, BLK>>>(peoff, peidx, phvout, nullptr, pS2, N_HEDGES);      // S2
    cudaStreamWaitEvent(0, evGE, 0);
    gemm_tiled_kernel<256, true><<<gemmE, 256, smem256>>>(
        pS2, efeat, pdeg, invDE, pGE, psi2_W, psi2_b, pE2, nullptr, N_HEDGES, 0);   // E2 = B*invDE + GE
    gemm_tiled_kernel<128, false><<<gemmE, 256, smem128>>>(
        pE2, nullptr, nullptr, nullptr, nullptr, We, nullptr, eout, nullptr, N_HEDGES, 1); // eout
}

// round 13
// speedup vs baseline: 1.1828x; 1.1828x over previous
#include <cuda_runtime.h>
#include <cuda_fp16.h>
#include <mma.h>
#include <cstdint>

using namespace nvcuda;

#define N_NODES 50000
#define N_HEDGES 10000
#define NNZ_INC 400000
#define NNZ_E 80000
#define NNZ_V 400000
#define D 128

#define NB_N 49
#define NB_V 49
#define NB_M 10
#define NB_E 10

// ---------------- scratch ----------------
__device__ float g_GE[(size_t)N_HEDGES * D];   // addend for B GEMM (fp32)
__device__ float g_c1[N_HEDGES];
__device__ float g_deg[N_HEDGES];

// fp16 working set
__device__ __half g_hvfeat[(size_t)N_NODES * D];
__device__ __half g_hefeat[(size_t)N_HEDGES * D];
__device__ __half g_hS1  [(size_t)N_HEDGES * D];
__device__ __half g_hS2  [(size_t)N_HEDGES * D];
__device__ __half g_hA   [(size_t)N_HEDGES * D];
__device__ __half g_hC   [(size_t)N_HEDGES * D];
__device__ __half g_hE2  [(size_t)N_HEDGES * D];
__device__ __half g_hV1  [(size_t)N_NODES * D];
__device__ __half g_hV2  [(size_t)N_NODES * D];
__device__ __half g_hV3  [(size_t)N_NODES * D];
__device__ __half g_hvout[(size_t)N_NODES * D];

// CSR scratch
__device__ int g_ecnt[N_HEDGES];  __device__ int g_eoff[N_HEDGES + 1];  __device__ int g_ecur[N_HEDGES];
__device__ int g_ncnt[N_NODES];   __device__ int g_noff[N_NODES + 1];   __device__ int g_ncur[N_NODES];
__device__ int g_vcnt[N_NODES];   __device__ int g_voff[N_NODES + 1];   __device__ int g_vcur[N_NODES];
__device__ int g_mcnt[N_HEDGES];  __device__ int g_moff[N_HEDGES + 1];  __device__ int g_mcur[N_HEDGES];
__device__ int   g_eidx[NNZ_INC];
__device__ int   g_nidx[NNZ_INC];
__device__ int   g_vidx[NNZ_V];
__device__ float g_vval[NNZ_V];
__device__ int   g_midx[NNZ_E];
__device__ float g_mval[NNZ_E];
__device__ int   g_bsumE[NB_E];
__device__ int   g_bsumNVM[NB_N + NB_V + NB_M];

// ---------------- helpers ----------------
__device__ __forceinline__ void sth4(__half* p, float4 v) {
    __half2 h0 = __floats2half2_rn(v.x, v.y);
    __half2 h1 = __floats2half2_rn(v.z, v.w);
    uint2 u;
    u.x = *(unsigned*)&h0;
    u.y = *(unsigned*)&h1;
    *(uint2*)p = u;
}
__device__ __forceinline__ void accum8(float4& a, float4& b, uint4 u) {
    __half2* h = (__half2*)&u;
    float2 f0 = __half22float2(h[0]), f1 = __half22float2(h[1]);
    float2 f2 = __half22float2(h[2]), f3 = __half22float2(h[3]);
    a.x += f0.x; a.y += f0.y; a.z += f1.x; a.w += f1.y;
    b.x += f2.x; b.y += f2.y; b.z += f3.x; b.w += f3.y;
}
__device__ __forceinline__ void faccum8(float4& a, float4& b, float s, uint4 u) {
    __half2* h = (__half2*)&u;
    float2 f0 = __half22float2(h[0]), f1 = __half22float2(h[1]);
    float2 f2 = __half22float2(h[2]), f3 = __half22float2(h[3]);
    a.x = fmaf(s, f0.x, a.x); a.y = fmaf(s, f0.y, a.y);
    a.z = fmaf(s, f1.x, a.z); a.w = fmaf(s, f1.y, a.w);
    b.x = fmaf(s, f2.x, b.x); b.y = fmaf(s, f2.y, b.y);
    b.z = fmaf(s, f3.x, b.z); b.w = fmaf(s, f3.y, b.w);
}
__device__ __forceinline__ void red16(float4& a) {
    a.x += __shfl_xor_sync(0xffffffffu, a.x, 16);
    a.y += __shfl_xor_sync(0xffffffffu, a.y, 16);
    a.z += __shfl_xor_sync(0xffffffffu, a.z, 16);
    a.w += __shfl_xor_sync(0xffffffffu, a.w, 16);
}
__device__ __forceinline__ void m4(float4& a, float4 c) {
    a.x += c.x; a.y += c.y; a.z += c.z; a.w += c.w;
}
__device__ __forceinline__ void sth8(__half* p, float4 a, float4 b) {
    __half2 h0 = __floats2half2_rn(a.x, a.y), h1 = __floats2half2_rn(a.z, a.w);
    __half2 h2 = __floats2half2_rn(b.x, b.y), h3 = __floats2half2_rn(b.z, b.w);
    uint4 u;
    u.x = *(unsigned*)&h0; u.y = *(unsigned*)&h1;
    u.z = *(unsigned*)&h2; u.w = *(unsigned*)&h3;
    *(uint4*)p = u;
}

// ---------------- input conversion ----------------
__global__ void conv_feat_kernel(const float* __restrict__ vf, const float* __restrict__ ef) {
    int i = blockIdx.x * blockDim.x + threadIdx.x;
    int stride = gridDim.x * blockDim.x;
    const int NV = N_NODES * D / 4, NE = N_HEDGES * D / 4;
    for (int k = i; k < NV; k += stride)
        sth4(g_hvfeat + (size_t)k * 4, ((const float4*)vf)[k]);
    for (int k = i; k < NE; k += stride)
        sth4(g_hefeat + (size_t)k * 4, ((const float4*)ef)[k]);
}

// ---------------- CSR build ----------------
__global__ void zeroE_kernel() {
    int i = blockIdx.x * blockDim.x + threadIdx.x;
    if (i < N_HEDGES) g_ecnt[i] = 0;
}
__global__ void zeroNVM_kernel() {
    int i = blockIdx.x * blockDim.x + threadIdx.x;
    int stride = gridDim.x * blockDim.x;
    for (int k = i; k < N_NODES; k += stride) { g_ncnt[k] = 0; g_vcnt[k] = 0; }
    for (int k = i; k < N_HEDGES; k += stride) g_mcnt[k] = 0;
}
__global__ void histE_kernel(const int* __restrict__ dst) {
    int k = blockIdx.x * blockDim.x + threadIdx.x;
    if (k < NNZ_INC) atomicAdd(&g_ecnt[__ldg(dst + k)], 1);
}
__global__ void histNVM_kernel(const int* __restrict__ src,
                               const int* __restrict__ vrows,
                               const int* __restrict__ mrows) {
    int k = blockIdx.x * blockDim.x + threadIdx.x;
    if (k < NNZ_INC) {
        atomicAdd(&g_ncnt[__ldg(src + k)], 1);
        atomicAdd(&g_vcnt[__ldg(vrows + k)], 1);
        if (k < NNZ_E) atomicAdd(&g_mcnt[__ldg(mrows + k)], 1);
    }
}
__device__ void scan_p1_body(const int* __restrict__ cnt, int* __restrict__ off,
                             int n, int lblk, int* __restrict__ bsum) {
    __shared__ int warpsum[8];
    int t = threadIdx.x;
    int lane = t & 31, wid = t >> 5;
    int base = lblk * 1024 + t * 4;
    int v0 = 0, v1 = 0, v2 = 0, v3 = 0;
    if (base + 3 < n) {
        int4 vv = *(const int4*)(cnt + base);
        v0 = vv.x; v1 = vv.y; v2 = vv.z; v3 = vv.w;
    } else {
        if (base     < n) v0 = cnt[base];
        if (base + 1 < n) v1 = cnt[base + 1];
        if (base + 2 < n) v2 = cnt[base + 2];
        if (base + 3 < n) v3 = cnt[base + 3];
    }
    int ts = v0 + v1 + v2 + v3;
    int incl = ts;
#pragma unroll
    for (int dlt = 1; dlt < 32; dlt <<= 1) {
        int u = __shfl_up_sync(0xffffffff, incl, dlt);
        if (lane >= dlt) incl += u;
    }
    if (lane == 31) warpsum[wid] = incl;
    __syncthreads();
    if (wid == 0) {
        int ws = (lane < 8) ? warpsum[lane] : 0;
        int wincl = ws;
#pragma unroll
        for (int dlt = 1; dlt < 8; dlt <<= 1) {
            int u = __shfl_up_sync(0xffffffff, wincl, dlt);
            if (lane >= dlt) wincl += u;
        }
        if (lane < 8) warpsum[lane] = wincl - ws;
        if (lane == 7) bsum[lblk] = wincl;
    }
    __syncthreads();
    int ex = warpsum[wid] + incl - ts;
    if (base     < n) off[base]     = ex;
    if (base + 1 < n) off[base + 1] = ex + v0;
    if (base + 2 < n) off[base + 2] = ex + v0 + v1;
    if (base + 3 < n) off[base + 3] = ex + v0 + v1 + v2;
}
__device__ void scan_p2_warp(int* bsum, int nblk, int* off, int n, int lane) {
    int carry = 0;
    for (int i0 = 0; i0 < nblk; i0 += 32) {
        int i = i0 + lane;
        int v = (i < nblk) ? bsum[i] : 0;
        int incl = v;
#pragma unroll
        for (int dlt = 1; dlt < 32; dlt <<= 1) {
            int u = __shfl_up_sync(0xffffffff, incl, dlt);
            if (lane >= dlt) incl += u;
        }
        if (i < nblk) bsum[i] = carry + incl - v;
        carry += __shfl_sync(0xffffffff, incl, 31);
    }
    if (lane == 0) off[n] = carry;
}
__device__ void scan_p3_body(int* __restrict__ off, int* __restrict__ cur,
                             int n, int lblk, const int* __restrict__ bsum) {
    int add = bsum[lblk];
    int base = lblk * 1024 + threadIdx.x * 4;
#pragma unroll
    for (int k = 0; k < 4; k++) {
        int i = base + k;
        if (i < n) { int v = off[i] + add; off[i] = v; cur[i] = v; }
    }
}
__device__ __forceinline__ void nvm_seg(int blk, const int*& cnt, int*& off, int*& cur,
                                        int& n, int& lblk, int*& bsum) {
    if (blk < NB_N)            { cnt = g_ncnt; off = g_noff; cur = g_ncur; n = N_NODES;  lblk = blk;               bsum = g_bsumNVM; }
    else if (blk < NB_N+NB_V)  { cnt = g_vcnt; off = g_voff; cur = g_vcur; n = N_NODES;  lblk = blk - NB_N;        bsum = g_bsumNVM + NB_N; }
    else                       { cnt = g_mcnt; off = g_moff; cur = g_mcur; n = N_HEDGES; lblk = blk - NB_N - NB_V; bsum = g_bsumNVM + NB_N + NB_V; }
}
__global__ void scanNVM_p1() {
    const int* cnt; int *off, *cur, *bsum; int n, lblk;
    nvm_seg(blockIdx.x, cnt, off, cur, n, lblk, bsum);
    scan_p1_body(cnt, off, n, lblk, bsum);
}
__global__ void scanNVM_p2() {
    int wid = threadIdx.x >> 5, lane = threadIdx.x & 31;
    if (wid == 0)      scan_p2_warp(g_bsumNVM,             NB_N, g_noff, N_NODES,  lane);
    else if (wid == 1) scan_p2_warp(g_bsumNVM + NB_N,      NB_V, g_voff, N_NODES,  lane);
    else if (wid == 2) scan_p2_warp(g_bsumNVM + NB_N+NB_V, NB_M, g_moff, N_HEDGES, lane);
}
__global__ void scanNVM_p3() {
    const int* cnt; int *off, *cur, *bsum; int n, lblk;
    nvm_seg(blockIdx.x, cnt, off, cur, n, lblk, bsum);
    scan_p3_body(off, cur, n, lblk, bsum);
}
__global__ void scanE_p1() { scan_p1_body(g_ecnt, g_eoff, N_HEDGES, blockIdx.x, g_bsumE); }
__global__ void scanE_p2() {
    if (threadIdx.x < 32) scan_p2_warp(g_bsumE, NB_E, g_eoff, N_HEDGES, threadIdx.x);
}
__global__ void scanE_p3() { scan_p3_body(g_eoff, g_ecur, N_HEDGES, blockIdx.x, g_bsumE); }

__global__ void fillE_kernel(const int* __restrict__ src, const int* __restrict__ dst) {
    int k = blockIdx.x * blockDim.x + threadIdx.x;
    if (k >= NNZ_INC) return;
    int d = __ldg(dst + k);
    int pe = atomicAdd(&g_ecur[d], 1);
    g_eidx[pe] = __ldg(src + k);
}
__global__ void fillNVM_kernel(const int* __restrict__ src, const int* __restrict__ dst,
                               const int* __restrict__ vrows, const int* __restrict__ vcols,
                               const float* __restrict__ vvals,
                               const int* __restrict__ mrows, const int* __restrict__ mcols,
                               const float* __restrict__ mvals) {
    int k = blockIdx.x * blockDim.x + threadIdx.x;
    if (k >= NNZ_INC) return;
    int s = __ldg(src + k), r = __ldg(vrows + k);
    int pn = atomicAdd(&g_ncur[s], 1);
    g_nidx[pn] = __ldg(dst + k);
    int pv = atomicAdd(&g_vcur[r], 1);
    g_vidx[pv] = __ldg(vcols + k);
    g_vval[pv] = __ldg(vvals + k);
    if (k < NNZ_E) {
        int mr = __ldg(mrows + k);
        int pm = atomicAdd(&g_mcur[mr], 1);
        g_midx[pm] = __ldg(mcols + k);
        g_mval[pm] = __ldg(mvals + k);
    }
}

// ---------------- pair-mode gathers (half-warp per entry, 16B loads, unroll 8) -------
// hS1[e] = sum invDV[s]*hvfeat[s]; c1[e]; deg[e]
__global__ void edge_gather1_h(const float* __restrict__ invDV) {
    int w = (blockIdx.x * blockDim.x + threadIdx.x) >> 5;
    int lane = threadIdx.x & 31;
    if (w >= N_HEDGES) return;
    int half = lane >> 4, hl = lane & 15;
    int b = g_eoff[w], e = g_eoff[w + 1];
    float4 aA = make_float4(0.f,0.f,0.f,0.f), aB = aA, cA = aA, cB = aA;
    float cs = 0.f;
    int j = b;
    for (; j + 8 <= e; j += 8) {
        int s0 = g_eidx[j     + half];
        int s1 = g_eidx[j + 2 + half];
        int s2 = g_eidx[j + 4 + half];
        int s3 = g_eidx[j + 6 + half];
        float i0 = invDV[s0], i1 = invDV[s1], i2 = invDV[s2], i3 = invDV[s3];
        uint4 u0 = *(const uint4*)(g_hvfeat + (size_t)s0 * D + hl * 8);
        uint4 u1 = *(const uint4*)(g_hvfeat + (size_t)s1 * D + hl * 8);
        uint4 u2 = *(const uint4*)(g_hvfeat + (size_t)s2 * D + hl * 8);
        uint4 u3 = *(const uint4*)(g_hvfeat + (size_t)s3 * D + hl * 8);
        faccum8(aA, aB, i0, u0);
        faccum8(cA, cB, i1, u1);
        faccum8(aA, aB, i2, u2);
        faccum8(cA, cB, i3, u3);
        if (hl == 0) cs += i0 + i1 + i2 + i3;
    }
    for (; j + 2 <= e; j += 2) {
        int s0 = g_eidx[j + half];
        float i0 = invDV[s0];
        uint4 u0 = *(const uint4*)(g_hvfeat + (size_t)s0 * D + hl * 8);
        faccum8(aA, aB, i0, u0);
        if (hl == 0) cs += i0;
    }
    if (j < e && half == 0) {
        int s0 = g_eidx[j];
        float i0 = invDV[s0];
        uint4 u0 = *(const uint4*)(g_hvfeat + (size_t)s0 * D + hl * 8);
        faccum8(aA, aB, i0, u0);
        if (hl == 0) cs += i0;
    }
    m4(aA, cA); m4(aB, cB);
    red16(aA); red16(aB);
    cs += __shfl_xor_sync(0xffffffffu, cs, 16);
    if (half == 0) {
        sth8(g_hS1 + (size_t)w * D + hl * 8, aA, aB);
        if (hl == 0) { g_c1[w] = cs; g_deg[w] = (float)(e - b); }
    }
}

// Yh[r] = (baseh ? baseh[r] : 0) + sum Xh[idx[j]]   (fp16 out)
__global__ void gather_sum_h2h(const int* __restrict__ off, const int* __restrict__ idx,
                               const __half* __restrict__ Xh, const __half* __restrict__ baseh,
                               __half* __restrict__ Yh, int R) {
    int w = (blockIdx.x * blockDim.x + threadIdx.x) >> 5;
    int lane = threadIdx.x & 31;
    if (w >= R) return;
    int half = lane >> 4, hl = lane & 15;
    int b = off[w], e = off[w + 1];
    float4 aA = make_float4(0.f,0.f,0.f,0.f), aB = aA, cA = aA, cB = aA;
    int j = b;
    for (; j + 8 <= e; j += 8) {
        int s0 = idx[j     + half], s1 = idx[j + 2 + half];
        int s2 = idx[j + 4 + half], s3 = idx[j + 6 + half];
        uint4 u0 = *(const uint4*)(Xh + (size_t)s0 * D + hl * 8);
        uint4 u1 = *(const uint4*)(Xh + (size_t)s1 * D + hl * 8);
        uint4 u2 = *(const uint4*)(Xh + (size_t)s2 * D + hl * 8);
        uint4 u3 = *(const uint4*)(Xh + (size_t)s3 * D + hl * 8);
        accum8(aA, aB, u0);
        accum8(cA, cB, u1);
        accum8(aA, aB, u2);
        accum8(cA, cB, u3);
    }
    for (; j + 2 <= e; j += 2) {
        int s0 = idx[j + half];
        uint4 u0 = *(const uint4*)(Xh + (size_t)s0 * D + hl * 8);
        accum8(aA, aB, u0);
    }
    if (j < e && half == 0) {
        int s0 = idx[j];
        uint4 u0 = *(const uint4*)(Xh + (size_t)s0 * D + hl * 8);
        accum8(aA, aB, u0);
    }
    m4(aA, cA); m4(aB, cB);
    red16(aA); red16(aB);
    if (half == 0) {
        if (baseh) {
            uint4 ub = *(const uint4*)(baseh + (size_t)w * D + hl * 8);
            accum8(aA, aB, ub);
        }
        sth8(Yh + (size_t)w * D + hl * 8, aA, aB);
    }
}

// Yf[r] = sum Xh[idx[j]]   (fp32 out, used for GE addend)
__global__ void gather_sum_h2f(const int* __restrict__ off, const int* __restrict__ idx,
                               const __half* __restrict__ Xh, float* __restrict__ Yf, int R) {
    int w = (blockIdx.x * blockDim.x + threadIdx.x) >> 5;
    int lane = threadIdx.x & 31;
    if (w >= R) return;
    int half = lane >> 4, hl = lane & 15;
    int b = off[w], e = off[w + 1];
    float4 aA = make_float4(0.f,0.f,0.f,0.f), aB = aA, cA = aA, cB = aA;
    int j = b;
    for (; j + 8 <= e; j += 8) {
        int s0 = idx[j     + half], s1 = idx[j + 2 + half];
        int s2 = idx[j + 4 + half], s3 = idx[j + 6 + half];
        uint4 u0 = *(const uint4*)(Xh + (size_t)s0 * D + hl * 8);
        uint4 u1 = *(const uint4*)(Xh + (size_t)s1 * D + hl * 8);
        uint4 u2 = *(const uint4*)(Xh + (size_t)s2 * D + hl * 8);
        uint4 u3 = *(const uint4*)(Xh + (size_t)s3 * D + hl * 8);
        accum8(aA, aB, u0);
        accum8(cA, cB, u1);
        accum8(aA, aB, u2);
        accum8(cA, cB, u3);
    }
    for (; j + 2 <= e; j += 2) {
        int s0 = idx[j + half];
        uint4 u0 = *(const uint4*)(Xh + (size_t)s0 * D + hl * 8);
        accum8(aA, aB, u0);
    }
    if (j < e && half == 0) {
        int s0 = idx[j];
        uint4 u0 = *(const uint4*)(Xh + (size_t)s0 * D + hl * 8);
        accum8(aA, aB, u0);
    }
    m4(aA, cA); m4(aB, cB);
    red16(aA); red16(aB);
    if (half == 0) {
        float* yp = Yf + (size_t)w * D + hl * 8;
        *(float4*)yp = aA;
        *(float4*)(yp + 4) = aB;
    }
}

// Yh[r] = sum wv[j] * Xh[idx[j]]
__global__ void gather_wsum_h2h(const int* __restrict__ off, const int* __restrict__ idx,
                                const float* __restrict__ wv, const __half* __restrict__ Xh,
                                __half* __restrict__ Yh, int R) {
    int w = (blockIdx.x * blockDim.x + threadIdx.x) >> 5;
    int lane = threadIdx.x & 31;
    if (w >= R) return;
    int half = lane >> 4, hl = lane & 15;
    int b = off[w], e = off[w + 1];
    float4 aA = make_float4(0.f,0.f,0.f,0.f), aB = aA, cA = aA, cB = aA;
    int j = b;
    for (; j + 8 <= e; j += 8) {
        int s0 = idx[j     + half], s1 = idx[j + 2 + half];
        int s2 = idx[j + 4 + half], s3 = idx[j + 6 + half];
        float w0 = wv[j     + half], w1 = wv[j + 2 + half];
        float w2 = wv[j + 4 + half], w3 = wv[j + 6 + half];
        uint4 u0 = *(const uint4*)(Xh + (size_t)s0 * D + hl * 8);
        uint4 u1 = *(const uint4*)(Xh + (size_t)s1 * D + hl * 8);
        uint4 u2 = *(const uint4*)(Xh + (size_t)s2 * D + hl * 8);
        uint4 u3 = *(const uint4*)(Xh + (size_t)s3 * D + hl * 8);
        faccum8(aA, aB, w0, u0);
        faccum8(cA, cB, w1, u1);
        faccum8(aA, aB, w2, u2);
        faccum8(cA, cB, w3, u3);
    }
    for (; j + 2 <= e; j += 2) {
        int s0 = idx[j + half];
        float w0 = wv[j + half];
        uint4 u0 = *(const uint4*)(Xh + (size_t)s0 * D + hl * 8);
        faccum8(aA, aB, w0, u0);
    }
    if (j < e && half == 0) {
        int s0 = idx[j];
        float w0 = wv[j];
        uint4 u0 = *(const uint4*)(Xh + (size_t)s0 * D + hl * 8);
        faccum8(aA, aB, w0, u0);
    }
    m4(aA, cA); m4(aB, cB);
    red16(aA); red16(aB);
    if (half == 0) sth8(Yh + (size_t)w * D + hl * 8, aA, aB);
}

// ---------------- tensor-core GEMM (wmma m16n16k16, fp16 in, fp32 accum) -------------
// Y = act( ([Xh | coef*efh] @ W^T + coef*b) * oscale + addend )
// Block: 64 rows x 128 cols, 256 threads = 8 warps (4 row-bands x 2 col-halves).
#define GEMM_RT 64
template <int K, bool CONCAT>
__global__ void gemm_wmma_kernel(const __half* __restrict__ Xh, const __half* __restrict__ efh,
                                 const float* __restrict__ coef, const float* __restrict__ oscale,
                                 const float* __restrict__ addend,
                                 const float* __restrict__ W,    // [128, K] fp32 row-major
                                 const float* __restrict__ bias,
                                 float* __restrict__ Y, __half* __restrict__ Yh,
                                 int R, int do_relu) {
    extern __shared__ char shraw[];
    __half* sW = (__half*)shraw;                              // [128*K] same layout as W -> col-major [KxNcols], ld=K
    __half* sX = (__half*)(shraw + (size_t)128 * K * 2);      // [64*K] row-major, ld=K
    float*  sC = (float*)(shraw + (size_t)128 * K * 2 + (size_t)GEMM_RT * K * 2);  // [64*132]
    const int tid = threadIdx.x;
    const int row0 = blockIdx.x * GEMM_RT;

    // stage W -> fp16 (layout preserved)
    for (int i = tid * 4; i < 128 * K; i += 256 * 4) {
        float4 wv = *(const float4*)(W + i);
        sth4(sW + i, wv);
    }
    // stage X tile -> fp16 row-major [64][K]
    constexpr int NH8 = K / 8;
    for (int i = tid; i < GEMM_RT * NH8; i += 256) {
        int row = i / NH8, h8 = i - row * NH8;
        int kk = h8 * 8;
        int gr = row0 + row;
        uint4 u = make_uint4(0u, 0u, 0u, 0u);
        if (gr < R) {
            if (!CONCAT || kk < 128) {
                u = *(const uint4*)(Xh + (size_t)gr * 128 + kk);
            } else {
                float cf = coef[gr];
                uint4 ue = *(const uint4*)(efh + (size_t)gr * 128 + (kk - 128));
                __half2* hp = (__half2*)&ue;
                __half2* op = (__half2*)&u;
#pragma unroll
                for (int q = 0; q < 4; q++) {
                    float2 f = __half22float2(hp[q]);
                    op[q] = __floats2half2_rn(f.x * cf, f.y * cf);
                }
            }
        }
        *(uint4*)(sX + (size_t)row * K + kk) = u;
    }
    __syncthreads();

    // mma: warp (wr in 0..3 -> 16-row band; wc in 0..1 -> 64-col half)
    int wid = tid >> 5;
    int wr = wid & 3, wc = wid >> 2;
    wmma::fragment<wmma::accumulator, 16, 16, 16, float> cf[4];
#pragma unroll
    for (int c = 0; c < 4; c++) wmma::fill_fragment(cf[c], 0.0f);
    wmma::fragment<wmma::matrix_a, 16, 16, 16, __half, wmma::row_major> af;
    wmma::fragment<wmma::matrix_b, 16, 16, 16, __half, wmma::col_major> bf;
    const __half* xa = sX + (size_t)(wr * 16) * K;
    for (int k0 = 0; k0 < K; k0 += 16) {
        wmma::load_matrix_sync(af, xa + k0, K);
#pragma unroll
        for (int c = 0; c < 4; c++) {
            int col = wc * 64 + c * 16;
            wmma::load_matrix_sync(bf, sW + (size_t)col * K + k0, K);
            wmma::mma_sync(cf[c], af, bf, cf[c]);
        }
    }
#pragma unroll
    for (int c = 0; c < 4; c++) {
        int col = wc * 64 + c * 16;
        wmma::store_matrix_sync(sC + (size_t)(wr * 16) * 132 + col, cf[c], 132, wmma::mem_row_major);
    }
    __syncthreads();

    // epilogue
    int tc = tid & 31;      // col group (4 cols)
    int trr = tid >> 5;     // row stride 8
    int c0 = tc * 4;
    float4 bv = make_float4(0.f, 0.f, 0.f, 0.f);
    if (bias) bv = *(const float4*)(bias + c0);
    for (int rr = trr; rr < GEMM_RT; rr += 8) {
        int row = row0 + rr;
        if (row >= R) continue;
        float4 o = *(float4*)(sC + (size_t)rr * 132 + c0);
        if (bias) {
            float cfv = coef ? coef[row] : 1.f;
            o.x = fmaf(cfv, bv.x, o.x); o.y = fmaf(cfv, bv.y, o.y);
            o.z = fmaf(cfv, bv.z, o.z); o.w = fmaf(cfv, bv.w, o.w);
        }
        if (oscale) {
            float os = oscale[row];
            o.x *= os; o.y *= os; o.z *= os; o.w *= os;
        }
        if (addend) {
            float4 ad = *(const float4*)(addend + (size_t)row * 128 + c0);
            o.x += ad.x; o.y += ad.y; o.z += ad.z; o.w += ad.w;
        }
        if (do_relu) {
            o.x = fmaxf(o.x, 0.f); o.y = fmaxf(o.y, 0.f);
            o.z = fmaxf(o.z, 0.f); o.w = fmaxf(o.w, 0.f);
        }
        if (Y)  *(float4*)(Y + (size_t)row * 128 + c0) = o;
        if (Yh) sth4(Yh + (size_t)row * 128 + c0, o);
    }
}

// ---------------- launch ----------------
extern "C" void kernel_launch(void* const* d_in, const int* in_sizes, int n_in,
                              void* d_out, int out_size) {
    const float* vfeat    = (const float*)d_in[0];
    const float* efeat    = (const float*)d_in[1];
    const float* invDV    = (const float*)d_in[2];
    const float* invDE    = (const float*)d_in[3];
    const int*   inc_src  = (const int*)d_in[4];
    const int*   inc_dst  = (const int*)d_in[5];
    const int*   emat_rows = (const int*)d_in[6];
    const int*   emat_cols = (const int*)d_in[7];
    const float* emat_vals = (const float*)d_in[8];
    const int*   vmat_rows = (const int*)d_in[9];
    const int*   vmat_cols = (const int*)d_in[10];
    const float* vmat_vals = (const float*)d_in[11];
    const float* Wv      = (const float*)d_in[12];
    const float* We      = (const float*)d_in[13];
    const float* psi1_W  = (const float*)d_in[14];
    const float* psi1_b  = (const float*)d_in[15];
    const float* psi2_W  = (const float*)d_in[16];
    const float* psi2_b  = (const float*)d_in[17];

    float* out  = (float*)d_out;
    float* vout = out;
    float* eout = out + (size_t)N_NODES * D;

    float *pGE, *pc1, *pdeg;
    int *peoff, *peidx, *pnoff, *pnidx, *pvoff, *pvidx, *pmoff, *pmidx;
    float *pvval, *pmval;
    __half *phS1, *phS2, *phA, *phC, *phE2, *phV1, *phV2, *phV3, *phvout, *phvfeat, *phefeat;
    cudaGetSymbolAddress((void**)&pGE, g_GE);
    cudaGetSymbolAddress((void**)&pc1, g_c1);
    cudaGetSymbolAddress((void**)&pdeg, g_deg);
    cudaGetSymbolAddress((void**)&peoff, g_eoff);
    cudaGetSymbolAddress((void**)&peidx, g_eidx);
    cudaGetSymbolAddress((void**)&pnoff, g_noff);
    cudaGetSymbolAddress((void**)&pnidx, g_nidx);
    cudaGetSymbolAddress((void**)&pvoff, g_voff);
    cudaGetSymbolAddress((void**)&pvidx, g_vidx);
    cudaGetSymbolAddress((void**)&pmoff, g_moff);
    cudaGetSymbolAddress((void**)&pmidx, g_midx);
    cudaGetSymbolAddress((void**)&pvval, g_vval);
    cudaGetSymbolAddress((void**)&pmval, g_mval);
    cudaGetSymbolAddress((void**)&phS1,  g_hS1);
    cudaGetSymbolAddress((void**)&phS2,  g_hS2);
    cudaGetSymbolAddress((void**)&phA,   g_hA);
    cudaGetSymbolAddress((void**)&phC,   g_hC);
    cudaGetSymbolAddress((void**)&phE2,  g_hE2);
    cudaGetSymbolAddress((void**)&phV1,  g_hV1);
    cudaGetSymbolAddress((void**)&phV2,  g_hV2);
    cudaGetSymbolAddress((void**)&phV3,  g_hV3);
    cudaGetSymbolAddress((void**)&phvout, g_hvout);
    cudaGetSymbolAddress((void**)&phvfeat, g_hvfeat);
    cudaGetSymbolAddress((void**)&phefeat, g_hefeat);

    size_t smemG256 = (size_t)128 * 256 * 2 + (size_t)GEMM_RT * 256 * 2 + (size_t)GEMM_RT * 132 * 4;
    size_t smemG128 = (size_t)128 * 128 * 2 + (size_t)GEMM_RT * 128 * 2 + (size_t)GEMM_RT * 132 * 4;
    cudaFuncSetAttribute(gemm_wmma_kernel<256, true>,
                         cudaFuncAttributeMaxDynamicSharedMemorySize, (int)smemG256);
    cudaFuncSetAttribute(gemm_wmma_kernel<128, false>,
                         cudaFuncAttributeMaxDynamicSharedMemorySize, (int)smemG128);

    static cudaStream_t s1 = nullptr;
    static cudaEvent_t evRoot = nullptr, evConv = nullptr, evM = nullptr, evV2 = nullptr;
    static cudaEvent_t evECSR = nullptr, evGE = nullptr;
    if (s1 == nullptr) {
        cudaStreamCreateWithFlags(&s1, cudaStreamNonBlocking);
        cudaEventCreateWithFlags(&evRoot, cudaEventDisableTiming);
        cudaEventCreateWithFlags(&evConv, cudaEventDisableTiming);
        cudaEventCreateWithFlags(&evM,    cudaEventDisableTiming);
        cudaEventCreateWithFlags(&evV2,   cudaEventDisableTiming);
        cudaEventCreateWithFlags(&evECSR, cudaEventDisableTiming);
        cudaEventCreateWithFlags(&evGE,   cudaEventDisableTiming);
    }

    const int BLK = 256;
    int ew = (N_HEDGES + 7) / 8;
    int nw = (N_NODES + 7) / 8;
    int gemmN = (N_NODES + GEMM_RT - 1) / GEMM_RT;
    int gemmE = (N_HEDGES + GEMM_RT - 1) / GEMM_RT;
    int nnz_blk = (NNZ_INC + BLK - 1) / BLK;

    cudaEventRecord(evRoot, 0);
    cudaStreamWaitEvent(s1, evRoot, 0);

    // --- stream B chain, part 1 ---
    conv_feat_kernel<<<1024, 256, 0, s1>>>(vfeat, efeat);
    cudaEventRecord(evConv, s1);
    zeroNVM_kernel<<<256, 256, 0, s1>>>();
    histNVM_kernel<<<nnz_blk, BLK, 0, s1>>>(inc_src, vmat_rows, emat_rows);
    scanNVM_p1<<<NB_N + NB_V + NB_M, 256, 0, s1>>>();
    scanNVM_p2<<<1, 96, 0, s1>>>();
    scanNVM_p3<<<NB_N + NB_V + NB_M, 256, 0, s1>>>();
    fillNVM_kernel<<<nnz_blk, BLK, 0, s1>>>(inc_src, inc_dst, vmat_rows, vmat_cols, vmat_vals,
                                            emat_rows, emat_cols, emat_vals);
    cudaEventRecord(evM, s1);
    gather_sum_h2h<<<nw, BLK, 0, s1>>>(pnoff, pnidx, phefeat, nullptr, phV2, N_NODES);   // hV2
    cudaEventRecord(evV2, s1);
    gather_wsum_h2h<<<nw, BLK, 0, s1>>>(pvoff, pvidx, pvval, phV2, phV3, N_NODES);       // hV3

    // --- stream A: E-CSR build ---
    zeroE_kernel<<<(N_HEDGES + 255) / 256, 256>>>();
    histE_kernel<<<nnz_blk, BLK>>>(inc_dst);
    scanE_p1<<<NB_E, 256>>>();
    scanE_p2<<<1, 32>>>();
    scanE_p3<<<NB_E, 256>>>();
    fillE_kernel<<<nnz_blk, BLK>>>(inc_src, inc_dst);
    cudaEventRecord(evECSR, 0);

    // --- stream B chain, part 2: GE gather (overlaps vout GEMM) ---
    cudaStreamWaitEvent(s1, evECSR, 0);
    gather_sum_h2f<<<ew, BLK, 0, s1>>>(peoff, peidx, phV3, pGE, N_HEDGES);               // GE (fp32)
    cudaEventRecord(evGE, s1);

    // --- stream A critical chain ---
    cudaStreamWaitEvent(0, evConv, 0);
    edge_gather1_h<<<ew, BLK>>>(invDV);                                                  // hS1, c1, deg
    gemm_wmma_kernel<256, true><<<gemmE, 256, smemG256>>>(
        phS1, phefeat, pc1, nullptr, nullptr, psi1_W, psi1_b,
        nullptr, phA, N_HEDGES, 0);                                                      // hA
    cudaStreamWaitEvent(0, evM, 0);
    gather_wsum_h2h<<<ew, BLK>>>(pmoff, pmidx, pmval, phA, phC, N_HEDGES);               // hC
    cudaStreamWaitEvent(0, evV2, 0);
    gather_sum_h2h<<<nw, BLK>>>(pnoff, pnidx, phC, phV2, phV1, N_NODES);                 // hV1 = hV2 + ΣhC
    gemm_wmma_kernel<128, false><<<gemmN, 256, smemG128>>>(
        phV1, nullptr, nullptr, nullptr, nullptr, Wv, nullptr,
        vout, phvout, N_NODES, 1);                                                       // vout (+h)
    gather_sum_h2h<<<ew, BLK>>>(peoff, peidx, phvout, nullptr, phS2, N_HEDGES);          // hS2
    cudaStreamWaitEvent(0, evGE, 0);
    gemm_wmma_kernel<256, true><<<gemmE, 256, smemG256>>>(
        phS2, phefeat, pdeg, invDE, pGE, psi2_W, psi2_b,
        nullptr, phE2, N_HEDGES, 0);                                                     // hE2
    gemm_wmma_kernel<128, false><<<gemmE, 256, smemG128>>>(
        phE2, nullptr, nullptr, nullptr, nullptr, We, nullptr,
        eout, nullptr, N_HEDGES, 1);                                                     // eout
}